// round 1
// baseline (speedup 1.0000x reference)
#include <cuda_runtime.h>

#define B_ 4
#define L_ 2048
#define D_ 1024
#define H_ 16
#define HD_ 64

// Scratch (allocation-free rule: __device__ globals)
__device__ float g_qh[B_*H_*L_*HD_];   // [b,h,l,hd]
__device__ float g_kh[B_*H_*L_*HD_];
__device__ float g_vh[B_*H_*L_*HD_];
__device__ float g_ao[B_*L_*D_];       // attention out, [b,l,d]

// C[m,n] = sum_k X[m,k] * W[n,k]   (torch Linear: y = x @ W^T)
// M = 8192, N = K = 1024. 128x128x8 tiles, 8x8 per thread.
__global__ void __launch_bounds__(256) gemm_xwt(const float* __restrict__ X,
        const float* __restrict__ W, float* __restrict__ Y, int head_layout)
{
    constexpr int BK = 8;
    __shared__ float As[BK][132];
    __shared__ float Bs[BK][132];
    const int tid = threadIdx.x;
    const int m0 = blockIdx.y * 128, n0 = blockIdx.x * 128;
    const int tx = tid & 15, ty = tid >> 4;
    const int lr = tid >> 1, lc = (tid & 1) * 4;

    float acc[8][8];
    #pragma unroll
    for (int i = 0; i < 8; i++)
        #pragma unroll
        for (int j = 0; j < 8; j++) acc[i][j] = 0.f;

    const float* Xp = X + (size_t)(m0 + lr) * D_ + lc;
    const float* Wp = W + (size_t)(n0 + lr) * D_ + lc;

    for (int k0 = 0; k0 < D_; k0 += BK) {
        float4 av = *(const float4*)(Xp + k0);
        float4 bv = *(const float4*)(Wp + k0);
        As[lc+0][lr] = av.x; As[lc+1][lr] = av.y; As[lc+2][lr] = av.z; As[lc+3][lr] = av.w;
        Bs[lc+0][lr] = bv.x; Bs[lc+1][lr] = bv.y; Bs[lc+2][lr] = bv.z; Bs[lc+3][lr] = bv.w;
        __syncthreads();
        #pragma unroll
        for (int kk = 0; kk < BK; kk++) {
            float4 a0 = *(const float4*)&As[kk][ty*8];
            float4 a1 = *(const float4*)&As[kk][ty*8+4];
            float4 b0 = *(const float4*)&Bs[kk][tx*8];
            float4 b1 = *(const float4*)&Bs[kk][tx*8+4];
            float a[8] = {a0.x,a0.y,a0.z,a0.w,a1.x,a1.y,a1.z,a1.w};
            float b[8] = {b0.x,b0.y,b0.z,b0.w,b1.x,b1.y,b1.z,b1.w};
            #pragma unroll
            for (int i = 0; i < 8; i++)
                #pragma unroll
                for (int j = 0; j < 8; j++)
                    acc[i][j] = fmaf(a[i], b[j], acc[i][j]);
        }
        __syncthreads();
    }

    if (head_layout) {
        // write into [b, h, l, hd]; n = h*64+hd, m = b*2048 + l
        #pragma unroll
        for (int i = 0; i < 8; i++) {
            int m = m0 + ty*8 + i;
            int b = m >> 11, l = m & 2047;
            #pragma unroll
            for (int j = 0; j < 8; j++) {
                int n = n0 + tx*8 + j;
                int h = n >> 6, hd = n & 63;
                Y[(((size_t)b*H_ + h)*L_ + l)*HD_ + hd] = acc[i][j];
            }
        }
    } else {
        #pragma unroll
        for (int i = 0; i < 8; i++) {
            int m = m0 + ty*8 + i;
            #pragma unroll
            for (int j = 0; j < 8; j++)
                Y[(size_t)m*D_ + n0 + tx*8 + j] = acc[i][j];
        }
    }
}

// Flash attention, causal. One block = 32 query rows of one (b,h).
// 256 threads: row r = tid>>3 (0..31), lane-in-row t = tid&7.
// Each thread: 8 score cols (t*8..t*8+7) and 8 output dims (t*8..t*8+7).
__global__ void __launch_bounds__(256) attn_kernel(const float* __restrict__ qh,
        const float* __restrict__ kh, const float* __restrict__ vh,
        float* __restrict__ ao)
{
    __shared__ float Qs[32][65];
    __shared__ float KVs[64][65];
    __shared__ float Ps[32][65];
    const int tid = threadIdx.x;
    const int bh = blockIdx.y;          // b*H + h
    const int q0 = blockIdx.x * 32;
    const int r = tid >> 3, t = tid & 7;

    const float* Qb = qh + ((size_t)bh * L_ + q0) * HD_;
    const float* Kb = kh + (size_t)bh * L_ * HD_;
    const float* Vb = vh + (size_t)bh * L_ * HD_;

    // load Q tile (32x64)
    for (int e = tid; e < 32*16; e += 256) {
        int rr = e >> 4, c4 = (e & 15) * 4;
        float4 vq = *(const float4*)&Qb[rr*64 + c4];
        Qs[rr][c4] = vq.x; Qs[rr][c4+1] = vq.y; Qs[rr][c4+2] = vq.z; Qs[rr][c4+3] = vq.w;
    }

    float m_run = -1e30f, l_run = 0.f;
    float o[8];
    #pragma unroll
    for (int d = 0; d < 8; d++) o[d] = 0.f;

    const int ntiles = ((q0 + 31) >> 6) + 1;   // causal: only KV tiles touching s <= l
    for (int kt = 0; kt < ntiles; kt++) {
        __syncthreads();   // prev iter done reading Ps / KVs
        // load K tile (64x64)
        for (int e = tid; e < 64*16; e += 256) {
            int rr = e >> 4, c4 = (e & 15) * 4;
            float4 vk = *(const float4*)&Kb[(size_t)(kt*64 + rr)*64 + c4];
            KVs[rr][c4] = vk.x; KVs[rr][c4+1] = vk.y; KVs[rr][c4+2] = vk.z; KVs[rr][c4+3] = vk.w;
        }
        __syncthreads();

        // scores S[r][t*8+j] = Q[r,:] . K[c,:]
        float s[8];
        #pragma unroll
        for (int j = 0; j < 8; j++) s[j] = 0.f;
        #pragma unroll 8
        for (int kk = 0; kk < 64; kk++) {
            float qv = Qs[r][kk];
            #pragma unroll
            for (int j = 0; j < 8; j++)
                s[j] = fmaf(qv, KVs[t*8+j][kk], s[j]);
        }

        const bool last = (kt == ntiles - 1);   // only diagonal tile needs mask
        float mloc = -1e30f;
        #pragma unroll
        for (int j = 0; j < 8; j++) {
            s[j] *= 0.125f;                     // 1/sqrt(64)
            if (last && (kt*64 + t*8 + j) > (q0 + r)) s[j] = -1e30f;
            mloc = fmaxf(mloc, s[j]);
        }
        mloc = fmaxf(mloc, __shfl_xor_sync(0xffffffffu, mloc, 1));
        mloc = fmaxf(mloc, __shfl_xor_sync(0xffffffffu, mloc, 2));
        mloc = fmaxf(mloc, __shfl_xor_sync(0xffffffffu, mloc, 4));

        float m_new = fmaxf(m_run, mloc);
        float p[8];
        float sum = 0.f;
        #pragma unroll
        for (int j = 0; j < 8; j++) { p[j] = __expf(s[j] - m_new); sum += p[j]; }
        sum += __shfl_xor_sync(0xffffffffu, sum, 1);
        sum += __shfl_xor_sync(0xffffffffu, sum, 2);
        sum += __shfl_xor_sync(0xffffffffu, sum, 4);

        float corr = __expf(m_run - m_new);
        l_run = l_run * corr + sum;
        m_run = m_new;
        #pragma unroll
        for (int d = 0; d < 8; d++) o[d] *= corr;

        #pragma unroll
        for (int j = 0; j < 8; j++) Ps[r][t*8+j] = p[j];
        __syncthreads();   // scores done reading K; P visible

        // load V tile into same buffer
        for (int e = tid; e < 64*16; e += 256) {
            int rr = e >> 4, c4 = (e & 15) * 4;
            float4 vv = *(const float4*)&Vb[(size_t)(kt*64 + rr)*64 + c4];
            KVs[rr][c4] = vv.x; KVs[rr][c4+1] = vv.y; KVs[rr][c4+2] = vv.z; KVs[rr][c4+3] = vv.w;
        }
        __syncthreads();

        // O[r][t*8+d] += sum_c P[r][c] * V[c][t*8+d]
        #pragma unroll 8
        for (int c = 0; c < 64; c++) {
            float pv = Ps[r][c];
            #pragma unroll
            for (int d = 0; d < 8; d++)
                o[d] = fmaf(pv, KVs[c][t*8+d], o[d]);
        }
    }

    float inv = 1.f / l_run;
    const int b = bh >> 4, h = bh & 15;
    float* op = ao + ((size_t)b * L_ + q0 + r) * D_ + h * HD_ + t * 8;
    #pragma unroll
    for (int d = 0; d < 8; d++) op[d] = o[d] * inv;
}

extern "C" void kernel_launch(void* const* d_in, const int* in_sizes, int n_in,
                              void* d_out, int out_size)
{
    const float* q  = (const float*)d_in[0];
    const float* k  = (const float*)d_in[1];
    const float* v  = (const float*)d_in[2];
    // d_in[3] = mask (causal tril) — applied analytically
    const float* Wq = (const float*)d_in[4];
    const float* Wk = (const float*)d_in[5];
    const float* Wv = (const float*)d_in[6];
    const float* Wo = (const float*)d_in[7];
    float* out = (float*)d_out;

    float *qh, *kh, *vh, *ao;
    cudaGetSymbolAddress((void**)&qh, g_qh);
    cudaGetSymbolAddress((void**)&kh, g_kh);
    cudaGetSymbolAddress((void**)&vh, g_vh);
    cudaGetSymbolAddress((void**)&ao, g_ao);

    dim3 gg(D_/128, (B_*L_)/128);   // (8, 64)
    gemm_xwt<<<gg, 256>>>(q, Wq, qh, 1);
    gemm_xwt<<<gg, 256>>>(k, Wk, kh, 1);
    gemm_xwt<<<gg, 256>>>(v, Wv, vh, 1);
    attn_kernel<<<dim3(L_/32, B_*H_), 256>>>(qh, kh, vh, ao);
    gemm_xwt<<<gg, 256>>>(ao, Wo, out, 0);
}

// round 3
// speedup vs baseline: 3.9267x; 3.9267x over previous
#include <cuda_runtime.h>
#include <cstdint>
#include <cstddef>

#define B_ 4
#define L_ 2048
#define D_ 1024
#define H_ 16
#define HD_ 64

// Scratch (allocation-free rule: __device__ globals)
__device__ float g_qh[B_*H_*L_*HD_];   // [b,h,l,hd]
__device__ float g_kh[B_*H_*L_*HD_];
__device__ float g_vh[B_*H_*L_*HD_];
__device__ float g_ao[B_*L_*D_];       // attention out, [b,l,d]

// ---------------- helpers ----------------
__device__ __forceinline__ uint32_t s2u(const void* p) {
    uint32_t a;
    asm("{ .reg .u64 t; cvta.to.shared.u64 t, %1; cvt.u32.u64 %0, t; }" : "=r"(a) : "l"(p));
    return a;
}
__device__ __forceinline__ uint32_t f2tf32(float f) {
    uint32_t u;
    asm("cvt.rna.tf32.f32 %0, %1;" : "=r"(u) : "f"(f));
    return u;
}
__device__ __forceinline__ void mma_tf32_16x8x8(float* c, const uint32_t* a, const uint32_t* b) {
    asm volatile(
        "mma.sync.aligned.m16n8k8.row.col.f32.tf32.tf32.f32 "
        "{%0,%1,%2,%3}, {%4,%5,%6,%7}, {%8,%9}, {%0,%1,%2,%3};"
        : "+f"(c[0]), "+f"(c[1]), "+f"(c[2]), "+f"(c[3])
        : "r"(a[0]), "r"(a[1]), "r"(a[2]), "r"(a[3]), "r"(b[0]), "r"(b[1]));
}

// ---------------- tf32 mma.sync GEMM: Y[m,n] = sum_k X[m,k] * W[n,k] ----------------
// M=8192, N=K=1024. Block tile 128x128x32, 8 warps (4M x 2N), warp tile 32x64.
#define ASZ  (128 * 36)            // one stage of one operand, floats
#define GEMM_SMEM (4 * ASZ * 4)    // A0,A1,B0,B1 bytes = 73728
#define NIT  (D_ / 32)             // 32 k-iterations

__global__ void __launch_bounds__(256, 2)
gemm_mma(const float* __restrict__ X, const float* __restrict__ W,
         float* __restrict__ Y, int head_layout)
{
    extern __shared__ float sm[];
    const int tid = threadIdx.x;
    const int wid = tid >> 5, lane = tid & 31;
    const int wm = wid >> 1, wn = wid & 1;      // 4 x 2 warp grid
    const int g = lane >> 2, t4 = lane & 3;
    const int m0 = blockIdx.y * 128, n0 = blockIdx.x * 128;

    float acc[2][8][4];
    #pragma unroll
    for (int am = 0; am < 2; am++)
        #pragma unroll
        for (int na = 0; na < 8; na++)
            #pragma unroll
            for (int q = 0; q < 4; q++) acc[am][na][q] = 0.f;

    const float* Xa = X + (size_t)m0 * D_;
    const float* Wb = W + (size_t)n0 * D_;

    // stage s: As = sm + s*ASZ, Bs = sm + 2*ASZ + s*ASZ ; rows padded to pitch 36
    auto load_stage = [&](int ck, int s) {
        float* As = sm + s * ASZ;
        float* Bs = sm + 2 * ASZ + s * ASZ;
        #pragma unroll
        for (int i = 0; i < 4; i++) {
            int id = tid + i * 256;           // 1024 float4 chunks per operand
            int r = id >> 3, u = id & 7;      // row, 16B-chunk within 32 cols
            uint32_t da = s2u(As + r * 36 + u * 4);
            uint32_t db = s2u(Bs + r * 36 + u * 4);
            asm volatile("cp.async.cg.shared.global [%0], [%1], 16;"
                         :: "r"(da), "l"(Xa + (size_t)r * D_ + ck * 32 + u * 4));
            asm volatile("cp.async.cg.shared.global [%0], [%1], 16;"
                         :: "r"(db), "l"(Wb + (size_t)r * D_ + ck * 32 + u * 4));
        }
        asm volatile("cp.async.commit_group;");
    };

    load_stage(0, 0);

    for (int it = 0; it < NIT; it++) {
        if (it + 1 < NIT) {
            load_stage(it + 1, (it + 1) & 1);
            asm volatile("cp.async.wait_group 1;");
        } else {
            asm volatile("cp.async.wait_group 0;");
        }
        __syncthreads();

        const float* As = sm + (it & 1) * ASZ;
        const float* Bs = sm + 2 * ASZ + (it & 1) * ASZ;

        #pragma unroll
        for (int kk = 0; kk < 4; kk++) {
            const int c0 = kk * 8 + t4;
            uint32_t a[2][4];
            #pragma unroll
            for (int am = 0; am < 2; am++) {
                int r = wm * 32 + am * 16 + g;
                a[am][0] = f2tf32(As[r * 36 + c0]);
                a[am][1] = f2tf32(As[(r + 8) * 36 + c0]);
                a[am][2] = f2tf32(As[r * 36 + c0 + 4]);
                a[am][3] = f2tf32(As[(r + 8) * 36 + c0 + 4]);
            }
            uint32_t b[8][2];
            #pragma unroll
            for (int na = 0; na < 8; na++) {
                int n = wn * 64 + na * 8 + g;
                b[na][0] = f2tf32(Bs[n * 36 + c0]);
                b[na][1] = f2tf32(Bs[n * 36 + c0 + 4]);
            }
            #pragma unroll
            for (int am = 0; am < 2; am++)
                #pragma unroll
                for (int na = 0; na < 8; na++)
                    mma_tf32_16x8x8(acc[am][na], a[am], b[na]);
        }
        __syncthreads();
    }

    // epilogue: C layout c0:(r, 2t) c1:(r, 2t+1) c2:(r+8, 2t) c3:(r+8, 2t+1)
    #pragma unroll
    for (int am = 0; am < 2; am++) {
        int r = m0 + wm * 32 + am * 16 + g;
        #pragma unroll
        for (int na = 0; na < 8; na++) {
            int n = n0 + wn * 64 + na * 8 + 2 * t4;
            if (head_layout) {
                int b = r >> 11, l = r & 2047;
                int h = n >> 6, hd = n & 63;
                float* p0 = Y + (((size_t)b * H_ + h) * L_ + l) * HD_ + hd;
                p0[0] = acc[am][na][0]; p0[1] = acc[am][na][1];
                float* p1 = p0 + 8 * HD_ * 0 + (size_t)8 * HD_; // r+8 same b,h (l+8)
                p1 = Y + (((size_t)b * H_ + h) * L_ + (l + 8)) * HD_ + hd;
                p1[0] = acc[am][na][2]; p1[1] = acc[am][na][3];
            } else {
                float* p0 = Y + (size_t)r * D_ + n;
                p0[0] = acc[am][na][0]; p0[1] = acc[am][na][1];
                float* p1 = Y + (size_t)(r + 8) * D_ + n;
                p1[0] = acc[am][na][2]; p1[1] = acc[am][na][3];
            }
        }
    }
}

// ---------------- Flash attention (fp32, register-tiled 8x8) ----------------
// Block: 128 threads, Q tile 128 rows, KV tile 64. ty=tid>>3 (16), tx=tid&7 (8).
#define ATTN_SMEM ((64*132 + 64*68 + 64*68 + 64*132) * 4)

__global__ void __launch_bounds__(128) attn_tc(
        const float* __restrict__ qh, const float* __restrict__ kh,
        const float* __restrict__ vh, float* __restrict__ ao)
{
    extern __shared__ float sm[];
    float* QsT = sm;                 // [64][132] transposed: [kk][r]
    float* KsT = QsT + 64 * 132;     // [64][68]  transposed: [kk][c]
    float* Vs  = KsT + 64 * 68;      // [64][68]  natural:    [c][d]
    float* PsT = Vs  + 64 * 68;      // [64][132] transposed: [c][r]

    const int tid = threadIdx.x;
    const int bh = blockIdx.y;
    const int q0 = blockIdx.x * 128;
    const int ty = tid >> 3, tx = tid & 7;

    const float* Qb = qh + ((size_t)bh * L_ + q0) * HD_;
    const float* Kb = kh + (size_t)bh * L_ * HD_;
    const float* Vb = vh + (size_t)bh * L_ * HD_;

    for (int e = tid; e < 128 * 16; e += 128) {
        int r = e >> 4, k4 = (e & 15) * 4;
        float4 v = *(const float4*)(Qb + (size_t)r * 64 + k4);
        QsT[(k4 + 0) * 132 + r] = v.x;
        QsT[(k4 + 1) * 132 + r] = v.y;
        QsT[(k4 + 2) * 132 + r] = v.z;
        QsT[(k4 + 3) * 132 + r] = v.w;
    }

    float m_run[8], l_run[8], o[8][8];
    #pragma unroll
    for (int i = 0; i < 8; i++) {
        m_run[i] = -1e30f; l_run[i] = 0.f;
        #pragma unroll
        for (int j = 0; j < 8; j++) o[i][j] = 0.f;
    }

    const int ntiles = 2 * blockIdx.x + 2;
    for (int kt = 0; kt < ntiles; kt++) {
        __syncthreads();
        for (int e = tid; e < 64 * 16; e += 128) {
            int c = e >> 4, k4 = (e & 15) * 4;
            float4 kv = *(const float4*)(Kb + (size_t)(kt * 64 + c) * 64 + k4);
            KsT[(k4 + 0) * 68 + c] = kv.x;
            KsT[(k4 + 1) * 68 + c] = kv.y;
            KsT[(k4 + 2) * 68 + c] = kv.z;
            KsT[(k4 + 3) * 68 + c] = kv.w;
            float4 vv = *(const float4*)(Vb + (size_t)(kt * 64 + c) * 64 + k4);
            *(float4*)(Vs + c * 68 + k4) = vv;
        }
        __syncthreads();

        float s[8][8];
        #pragma unroll
        for (int i = 0; i < 8; i++)
            #pragma unroll
            for (int j = 0; j < 8; j++) s[i][j] = 0.f;
        #pragma unroll 4
        for (int kk = 0; kk < 64; kk++) {
            float4 a0 = *(const float4*)(QsT + kk * 132 + ty * 8);
            float4 a1 = *(const float4*)(QsT + kk * 132 + ty * 8 + 4);
            float4 b0 = *(const float4*)(KsT + kk * 68 + tx * 8);
            float4 b1 = *(const float4*)(KsT + kk * 68 + tx * 8 + 4);
            float a[8] = {a0.x, a0.y, a0.z, a0.w, a1.x, a1.y, a1.z, a1.w};
            float b[8] = {b0.x, b0.y, b0.z, b0.w, b1.x, b1.y, b1.z, b1.w};
            #pragma unroll
            for (int i = 0; i < 8; i++)
                #pragma unroll
                for (int j = 0; j < 8; j++)
                    s[i][j] = fmaf(a[i], b[j], s[i][j]);
        }

        const bool maskt = (kt >= ntiles - 2);
        #pragma unroll
        for (int i = 0; i < 8; i++) {
            const int rg = q0 + ty * 8 + i;
            float mloc = -1e30f;
            #pragma unroll
            for (int j = 0; j < 8; j++) {
                s[i][j] *= 0.125f;
                if (maskt && (kt * 64 + tx * 8 + j) > rg) s[i][j] = -1e30f;
                mloc = fmaxf(mloc, s[i][j]);
            }
            mloc = fmaxf(mloc, __shfl_xor_sync(0xffffffffu, mloc, 1));
            mloc = fmaxf(mloc, __shfl_xor_sync(0xffffffffu, mloc, 2));
            mloc = fmaxf(mloc, __shfl_xor_sync(0xffffffffu, mloc, 4));
            float m_new = fmaxf(m_run[i], mloc);
            float sum = 0.f;
            #pragma unroll
            for (int j = 0; j < 8; j++) { s[i][j] = __expf(s[i][j] - m_new); sum += s[i][j]; }
            sum += __shfl_xor_sync(0xffffffffu, sum, 1);
            sum += __shfl_xor_sync(0xffffffffu, sum, 2);
            sum += __shfl_xor_sync(0xffffffffu, sum, 4);
            float corr = __expf(m_run[i] - m_new);
            l_run[i] = l_run[i] * corr + sum;
            m_run[i] = m_new;
            #pragma unroll
            for (int j = 0; j < 8; j++) o[i][j] *= corr;
            #pragma unroll
            for (int j = 0; j < 8; j++)
                PsT[(tx * 8 + j) * 132 + ty * 8 + i] = s[i][j];
        }
        __syncthreads();

        #pragma unroll 4
        for (int c = 0; c < 64; c++) {
            float4 a0 = *(const float4*)(PsT + c * 132 + ty * 8);
            float4 a1 = *(const float4*)(PsT + c * 132 + ty * 8 + 4);
            float4 b0 = *(const float4*)(Vs + c * 68 + tx * 8);
            float4 b1 = *(const float4*)(Vs + c * 68 + tx * 8 + 4);
            float a[8] = {a0.x, a0.y, a0.z, a0.w, a1.x, a1.y, a1.z, a1.w};
            float b[8] = {b0.x, b0.y, b0.z, b0.w, b1.x, b1.y, b1.z, b1.w};
            #pragma unroll
            for (int i = 0; i < 8; i++)
                #pragma unroll
                for (int j = 0; j < 8; j++)
                    o[i][j] = fmaf(a[i], b[j], o[i][j]);
        }
    }

    const int b = bh >> 4, h = bh & 15;
    #pragma unroll
    for (int i = 0; i < 8; i++) {
        float inv = 1.f / l_run[i];
        float* op = ao + ((size_t)b * L_ + q0 + ty * 8 + i) * D_ + h * 64 + tx * 8;
        float4 w0 = make_float4(o[i][0] * inv, o[i][1] * inv, o[i][2] * inv, o[i][3] * inv);
        float4 w1 = make_float4(o[i][4] * inv, o[i][5] * inv, o[i][6] * inv, o[i][7] * inv);
        *(float4*)op = w0;
        *(float4*)(op + 4) = w1;
    }
}

// ---------------- launch ----------------
extern "C" void kernel_launch(void* const* d_in, const int* in_sizes, int n_in,
                              void* d_out, int out_size)
{
    const float* q  = (const float*)d_in[0];
    const float* k  = (const float*)d_in[1];
    const float* v  = (const float*)d_in[2];
    // d_in[3] = mask (causal tril) — applied analytically
    const float* Wq = (const float*)d_in[4];
    const float* Wk = (const float*)d_in[5];
    const float* Wv = (const float*)d_in[6];
    const float* Wo = (const float*)d_in[7];
    float* out = (float*)d_out;

    float *qh, *kh, *vh, *ao;
    cudaGetSymbolAddress((void**)&qh, g_qh);
    cudaGetSymbolAddress((void**)&kh, g_kh);
    cudaGetSymbolAddress((void**)&vh, g_vh);
    cudaGetSymbolAddress((void**)&ao, g_ao);

    cudaFuncSetAttribute(gemm_mma, cudaFuncAttributeMaxDynamicSharedMemorySize, GEMM_SMEM);
    cudaFuncSetAttribute(attn_tc, cudaFuncAttributeMaxDynamicSharedMemorySize, ATTN_SMEM);

    dim3 gg(D_ / 128, (B_ * L_) / 128);   // (8, 64)
    gemm_mma<<<gg, 256, GEMM_SMEM>>>(q, Wq, qh, 1);
    gemm_mma<<<gg, 256, GEMM_SMEM>>>(k, Wk, kh, 1);
    gemm_mma<<<gg, 256, GEMM_SMEM>>>(v, Wv, vh, 1);
    attn_tc<<<dim3(L_ / 128, B_ * H_), 128, ATTN_SMEM>>>(qh, kh, vh, ao);
    gemm_mma<<<gg, 256, GEMM_SMEM>>>(ao, Wo, out, 0);
}

// round 4
// speedup vs baseline: 7.1600x; 1.8234x over previous
#include <cuda_runtime.h>
#include <cstdint>
#include <cstddef>

#define B_ 4
#define L_ 2048
#define D_ 1024
#define H_ 16
#define HD_ 64

// Scratch (allocation-free rule: __device__ globals)
__device__ float g_qh[B_*H_*L_*HD_];   // [b,h,l,hd]
__device__ float g_kh[B_*H_*L_*HD_];
__device__ float g_vh[B_*H_*L_*HD_];
__device__ float g_ao[B_*L_*D_];       // attention out, [b,l,d]

// ---------------- helpers ----------------
__device__ __forceinline__ uint32_t s2u(const void* p) {
    uint32_t a;
    asm("{ .reg .u64 t; cvta.to.shared.u64 t, %1; cvt.u32.u64 %0, t; }" : "=r"(a) : "l"(p));
    return a;
}
__device__ __forceinline__ uint32_t f2tf32(float f) {
    uint32_t u;
    asm("cvt.rna.tf32.f32 %0, %1;" : "=r"(u) : "f"(f));
    return u;
}
__device__ __forceinline__ void mma_tf32_16x8x8(float* c, const uint32_t* a, const uint32_t* b) {
    asm volatile(
        "mma.sync.aligned.m16n8k8.row.col.f32.tf32.tf32.f32 "
        "{%0,%1,%2,%3}, {%4,%5,%6,%7}, {%8,%9}, {%0,%1,%2,%3};"
        : "+f"(c[0]), "+f"(c[1]), "+f"(c[2]), "+f"(c[3])
        : "r"(a[0]), "r"(a[1]), "r"(a[2]), "r"(a[3]), "r"(b[0]), "r"(b[1]));
}

// ---------------- tf32 mma.sync GEMM: Y[m,n] = sum_k X[m,k] * W[n,k] ----------------
#define ASZ  (128 * 36)
#define GEMM_SMEM (4 * ASZ * 4)
#define NIT  (D_ / 32)

__global__ void __launch_bounds__(256, 2)
gemm_mma(const float* __restrict__ X, const float* __restrict__ W,
         float* __restrict__ Y, int head_layout)
{
    extern __shared__ float sm[];
    const int tid = threadIdx.x;
    const int wid = tid >> 5, lane = tid & 31;
    const int wm = wid >> 1, wn = wid & 1;
    const int g = lane >> 2, t4 = lane & 3;
    const int m0 = blockIdx.y * 128, n0 = blockIdx.x * 128;

    float acc[2][8][4];
    #pragma unroll
    for (int am = 0; am < 2; am++)
        #pragma unroll
        for (int na = 0; na < 8; na++)
            #pragma unroll
            for (int q = 0; q < 4; q++) acc[am][na][q] = 0.f;

    const float* Xa = X + (size_t)m0 * D_;
    const float* Wb = W + (size_t)n0 * D_;

    auto load_stage = [&](int ck, int s) {
        float* As = sm + s * ASZ;
        float* Bs = sm + 2 * ASZ + s * ASZ;
        #pragma unroll
        for (int i = 0; i < 4; i++) {
            int id = tid + i * 256;
            int r = id >> 3, u = id & 7;
            uint32_t da = s2u(As + r * 36 + u * 4);
            uint32_t db = s2u(Bs + r * 36 + u * 4);
            asm volatile("cp.async.cg.shared.global [%0], [%1], 16;"
                         :: "r"(da), "l"(Xa + (size_t)r * D_ + ck * 32 + u * 4));
            asm volatile("cp.async.cg.shared.global [%0], [%1], 16;"
                         :: "r"(db), "l"(Wb + (size_t)r * D_ + ck * 32 + u * 4));
        }
        asm volatile("cp.async.commit_group;");
    };

    load_stage(0, 0);

    for (int it = 0; it < NIT; it++) {
        if (it + 1 < NIT) {
            load_stage(it + 1, (it + 1) & 1);
            asm volatile("cp.async.wait_group 1;");
        } else {
            asm volatile("cp.async.wait_group 0;");
        }
        __syncthreads();

        const float* As = sm + (it & 1) * ASZ;
        const float* Bs = sm + 2 * ASZ + (it & 1) * ASZ;

        #pragma unroll
        for (int kk = 0; kk < 4; kk++) {
            const int c0 = kk * 8 + t4;
            uint32_t a[2][4];
            #pragma unroll
            for (int am = 0; am < 2; am++) {
                int r = wm * 32 + am * 16 + g;
                a[am][0] = f2tf32(As[r * 36 + c0]);
                a[am][1] = f2tf32(As[(r + 8) * 36 + c0]);
                a[am][2] = f2tf32(As[r * 36 + c0 + 4]);
                a[am][3] = f2tf32(As[(r + 8) * 36 + c0 + 4]);
            }
            uint32_t b[8][2];
            #pragma unroll
            for (int na = 0; na < 8; na++) {
                int n = wn * 64 + na * 8 + g;
                b[na][0] = f2tf32(Bs[n * 36 + c0]);
                b[na][1] = f2tf32(Bs[n * 36 + c0 + 4]);
            }
            #pragma unroll
            for (int am = 0; am < 2; am++)
                #pragma unroll
                for (int na = 0; na < 8; na++)
                    mma_tf32_16x8x8(acc[am][na], a[am], b[na]);
        }
        __syncthreads();
    }

    #pragma unroll
    for (int am = 0; am < 2; am++) {
        int r = m0 + wm * 32 + am * 16 + g;
        #pragma unroll
        for (int na = 0; na < 8; na++) {
            int n = n0 + wn * 64 + na * 8 + 2 * t4;
            if (head_layout) {
                int b = r >> 11, l = r & 2047;
                int h = n >> 6, hd = n & 63;
                float* p0 = Y + (((size_t)b * H_ + h) * L_ + l) * HD_ + hd;
                p0[0] = acc[am][na][0]; p0[1] = acc[am][na][1];
                float* p1 = Y + (((size_t)b * H_ + h) * L_ + (l + 8)) * HD_ + hd;
                p1[0] = acc[am][na][2]; p1[1] = acc[am][na][3];
            } else {
                float* p0 = Y + (size_t)r * D_ + n;
                p0[0] = acc[am][na][0]; p0[1] = acc[am][na][1];
                float* p1 = Y + (size_t)(r + 8) * D_ + n;
                p1[0] = acc[am][na][2]; p1[1] = acc[am][na][3];
            }
        }
    }
}

// ---------------- tf32 mma.sync flash attention ----------------
// Block: 128 threads (4 warps), Q tile 128 rows (32/warp = 2 m16-tiles), KV tile 64.
// smem: Q[128][68] + 2 stages of (K[64][68], V[64][68]); all natural layout.
#define QP 68
#define KVST (64 * QP)
#define ATTN_SMEM ((128 * QP + 4 * KVST) * 4)

__global__ void __launch_bounds__(128, 2) attn_mma(
        const float* __restrict__ qh, const float* __restrict__ kh,
        const float* __restrict__ vh, float* __restrict__ ao)
{
    extern __shared__ float sm[];
    float* Qs = sm;
    float* KV = sm + 128 * QP;

    const int tid = threadIdx.x;
    const int wid = tid >> 5, lane = tid & 31;
    const int g = lane >> 2, t4 = lane & 3;
    const int bh = blockIdx.y, q0 = blockIdx.x * 128;

    const float* Qb = qh + ((size_t)bh * L_ + q0) * HD_;
    const float* Kb = kh + (size_t)bh * L_ * HD_;
    const float* Vb = vh + (size_t)bh * L_ * HD_;

    // Q tile -> smem (fp32, cvt at frag load)
    #pragma unroll
    for (int i = 0; i < 16; i++) {
        int e = tid + i * 128;
        int r = e >> 4, c4 = (e & 15) * 4;
        *(float4*)(Qs + r * QP + c4) = *(const float4*)(Qb + (size_t)r * 64 + c4);
    }

    auto ldkv = [&](int kt, int st) {
        float* Ks = KV + st * 2 * KVST;
        float* Vs = Ks + KVST;
        const float* kg = Kb + (size_t)kt * 64 * 64;
        const float* vg = Vb + (size_t)kt * 64 * 64;
        #pragma unroll
        for (int i = 0; i < 8; i++) {
            int e = tid + i * 128;
            int r = e >> 4, c = (e & 15) * 4;
            asm volatile("cp.async.cg.shared.global [%0], [%1], 16;"
                         :: "r"(s2u(Ks + r * QP + c)), "l"(kg + (size_t)r * 64 + c));
            asm volatile("cp.async.cg.shared.global [%0], [%1], 16;"
                         :: "r"(s2u(Vs + r * QP + c)), "l"(vg + (size_t)r * 64 + c));
        }
        asm volatile("cp.async.commit_group;");
    };

    float mrun[4], lrun[4], O[2][8][4];
    #pragma unroll
    for (int i = 0; i < 4; i++) { mrun[i] = -1e30f; lrun[i] = 0.f; }
    #pragma unroll
    for (int mt = 0; mt < 2; mt++)
        #pragma unroll
        for (int nt = 0; nt < 8; nt++)
            #pragma unroll
            for (int e = 0; e < 4; e++) O[mt][nt][e] = 0.f;

    const int ntiles = 2 * blockIdx.x + 2;
    ldkv(0, 0);

    const int srcA = (lane & ~3) | (t4 >> 1);
    const int srcB = srcA + 2;

    for (int kt = 0; kt < ntiles; kt++) {
        asm volatile("cp.async.wait_group 0;");
        __syncthreads();
        if (kt + 1 < ntiles) ldkv(kt + 1, (kt + 1) & 1);
        const float* Ks = KV + (kt & 1) * 2 * KVST;
        const float* Vs = Ks + KVST;

        // ---- S = Q K^T ----
        float S[2][8][4];
        #pragma unroll
        for (int mt = 0; mt < 2; mt++)
            #pragma unroll
            for (int nt = 0; nt < 8; nt++)
                #pragma unroll
                for (int e = 0; e < 4; e++) S[mt][nt][e] = 0.f;

        #pragma unroll
        for (int kc = 0; kc < 8; kc++) {
            uint32_t af[2][4];
            #pragma unroll
            for (int mt = 0; mt < 2; mt++) {
                int r = wid * 32 + mt * 16 + g;
                af[mt][0] = f2tf32(Qs[r * QP + kc * 8 + t4]);
                af[mt][1] = f2tf32(Qs[(r + 8) * QP + kc * 8 + t4]);
                af[mt][2] = f2tf32(Qs[r * QP + kc * 8 + t4 + 4]);
                af[mt][3] = f2tf32(Qs[(r + 8) * QP + kc * 8 + t4 + 4]);
            }
            #pragma unroll
            for (int nt = 0; nt < 8; nt++) {
                uint32_t bf[2];
                bf[0] = f2tf32(Ks[(nt * 8 + g) * QP + kc * 8 + t4]);
                bf[1] = f2tf32(Ks[(nt * 8 + g) * QP + kc * 8 + t4 + 4]);
                mma_tf32_16x8x8(S[0][nt], af[0], bf);
                mma_tf32_16x8x8(S[1][nt], af[1], bf);
            }
        }

        // ---- online softmax (rows g, g+8 per m-tile) ----
        const bool maskt = (kt >= ntiles - 2);
        #pragma unroll
        for (int mt = 0; mt < 2; mt++)
            #pragma unroll
            for (int rr = 0; rr < 2; rr++) {
                const int si = mt * 2 + rr;
                const int rowg = q0 + wid * 32 + mt * 16 + rr * 8 + g;
                float mloc = -1e30f;
                #pragma unroll
                for (int nt = 0; nt < 8; nt++)
                    #pragma unroll
                    for (int e = 0; e < 2; e++) {
                        float v = S[mt][nt][rr * 2 + e] * 0.125f;
                        if (maskt && (kt * 64 + nt * 8 + 2 * t4 + e) > rowg) v = -1e30f;
                        S[mt][nt][rr * 2 + e] = v;
                        mloc = fmaxf(mloc, v);
                    }
                mloc = fmaxf(mloc, __shfl_xor_sync(0xffffffffu, mloc, 1));
                mloc = fmaxf(mloc, __shfl_xor_sync(0xffffffffu, mloc, 2));
                float mnew = fmaxf(mrun[si], mloc);
                float corr = __expf(mrun[si] - mnew);
                float sum = 0.f;
                #pragma unroll
                for (int nt = 0; nt < 8; nt++)
                    #pragma unroll
                    for (int e = 0; e < 2; e++) {
                        float p = __expf(S[mt][nt][rr * 2 + e] - mnew);
                        S[mt][nt][rr * 2 + e] = p;
                        sum += p;
                    }
                sum += __shfl_xor_sync(0xffffffffu, sum, 1);
                sum += __shfl_xor_sync(0xffffffffu, sum, 2);
                lrun[si] = lrun[si] * corr + sum;
                mrun[si] = mnew;
                #pragma unroll
                for (int nt = 0; nt < 8; nt++)
                    #pragma unroll
                    for (int e = 0; e < 2; e++)
                        O[mt][nt][rr * 2 + e] *= corr;
            }

        // ---- P -> tf32 in place ----
        #pragma unroll
        for (int mt = 0; mt < 2; mt++)
            #pragma unroll
            for (int nt = 0; nt < 8; nt++)
                #pragma unroll
                for (int e = 0; e < 4; e++)
                    S[mt][nt][e] = __uint_as_float(f2tf32(S[mt][nt][e]));

        // ---- O += P V  (C-frag -> A-frag via quad shuffles) ----
        #pragma unroll
        for (int kc = 0; kc < 8; kc++) {
            uint32_t a[2][4];
            #pragma unroll
            for (int mt = 0; mt < 2; mt++) {
                float v0 = __shfl_sync(0xffffffffu, S[mt][kc][0], srcA);
                float v1 = __shfl_sync(0xffffffffu, S[mt][kc][1], srcA);
                float v2 = __shfl_sync(0xffffffffu, S[mt][kc][2], srcA);
                float v3 = __shfl_sync(0xffffffffu, S[mt][kc][3], srcA);
                float w0 = __shfl_sync(0xffffffffu, S[mt][kc][0], srcB);
                float w1 = __shfl_sync(0xffffffffu, S[mt][kc][1], srcB);
                float w2 = __shfl_sync(0xffffffffu, S[mt][kc][2], srcB);
                float w3 = __shfl_sync(0xffffffffu, S[mt][kc][3], srcB);
                a[mt][0] = __float_as_uint((t4 & 1) ? v1 : v0);
                a[mt][1] = __float_as_uint((t4 & 1) ? v3 : v2);
                a[mt][2] = __float_as_uint((t4 & 1) ? w1 : w0);
                a[mt][3] = __float_as_uint((t4 & 1) ? w3 : w2);
            }
            #pragma unroll
            for (int nt = 0; nt < 8; nt++) {
                uint32_t bf[2];
                bf[0] = f2tf32(Vs[(kc * 8 + t4) * QP + nt * 8 + g]);
                bf[1] = f2tf32(Vs[(kc * 8 + t4 + 4) * QP + nt * 8 + g]);
                mma_tf32_16x8x8(O[0][nt], a[0], bf);
                mma_tf32_16x8x8(O[1][nt], a[1], bf);
            }
        }
    }

    // ---- epilogue: normalize + write [b, l, d] ----
    const int b = bh >> 4, h = bh & 15;
    #pragma unroll
    for (int mt = 0; mt < 2; mt++)
        #pragma unroll
        for (int rr = 0; rr < 2; rr++) {
            const int si = mt * 2 + rr;
            float inv = 1.f / lrun[si];
            int row = q0 + wid * 32 + mt * 16 + rr * 8 + g;
            float* op = ao + ((size_t)b * L_ + row) * D_ + h * 64 + 2 * t4;
            #pragma unroll
            for (int nt = 0; nt < 8; nt++) {
                float2 w = make_float2(O[mt][nt][rr * 2] * inv, O[mt][nt][rr * 2 + 1] * inv);
                *(float2*)(op + nt * 8) = w;
            }
        }
}

// ---------------- launch ----------------
extern "C" void kernel_launch(void* const* d_in, const int* in_sizes, int n_in,
                              void* d_out, int out_size)
{
    const float* q  = (const float*)d_in[0];
    const float* k  = (const float*)d_in[1];
    const float* v  = (const float*)d_in[2];
    // d_in[3] = mask (causal tril) — applied analytically
    const float* Wq = (const float*)d_in[4];
    const float* Wk = (const float*)d_in[5];
    const float* Wv = (const float*)d_in[6];
    const float* Wo = (const float*)d_in[7];
    float* out = (float*)d_out;

    float *qh, *kh, *vh, *ao;
    cudaGetSymbolAddress((void**)&qh, g_qh);
    cudaGetSymbolAddress((void**)&kh, g_kh);
    cudaGetSymbolAddress((void**)&vh, g_vh);
    cudaGetSymbolAddress((void**)&ao, g_ao);

    cudaFuncSetAttribute(gemm_mma, cudaFuncAttributeMaxDynamicSharedMemorySize, GEMM_SMEM);
    cudaFuncSetAttribute(attn_mma, cudaFuncAttributeMaxDynamicSharedMemorySize, ATTN_SMEM);

    dim3 gg(D_ / 128, (B_ * L_) / 128);   // (8, 64)
    gemm_mma<<<gg, 256, GEMM_SMEM>>>(q, Wq, qh, 1);
    gemm_mma<<<gg, 256, GEMM_SMEM>>>(k, Wk, kh, 1);
    gemm_mma<<<gg, 256, GEMM_SMEM>>>(v, Wv, vh, 1);
    attn_mma<<<dim3(L_ / 128, B_ * H_), 128, ATTN_SMEM>>>(qh, kh, vh, ao);
    gemm_mma<<<gg, 256, GEMM_SMEM>>>(ao, Wo, out, 0);
}

// round 5
// speedup vs baseline: 8.5322x; 1.1916x over previous
#include <cuda_runtime.h>
#include <cstdint>
#include <cstddef>

#define B_ 4
#define L_ 2048
#define D_ 1024
#define H_ 16
#define HD_ 64

// Scratch (allocation-free rule: __device__ globals)
__device__ float g_qh[B_*H_*L_*HD_];   // [b,h,l,hd]  (tf32-rounded, pre-scaled 0.125)
__device__ float g_kh[B_*H_*L_*HD_];   // tf32-rounded
__device__ float g_vh[B_*H_*L_*HD_];   // tf32-rounded
__device__ float g_ao[B_*L_*D_];       // attention out, [b,l,d]

// ---------------- helpers ----------------
__device__ __forceinline__ uint32_t s2u(const void* p) {
    uint32_t a;
    asm("{ .reg .u64 t; cvta.to.shared.u64 t, %1; cvt.u32.u64 %0, t; }" : "=r"(a) : "l"(p));
    return a;
}
__device__ __forceinline__ uint32_t f2tf32(float f) {
    uint32_t u;
    asm("cvt.rna.tf32.f32 %0, %1;" : "=r"(u) : "f"(f));
    return u;
}
__device__ __forceinline__ void mma_tf32_16x8x8(float* c, const uint32_t* a, const uint32_t* b) {
    asm volatile(
        "mma.sync.aligned.m16n8k8.row.col.f32.tf32.tf32.f32 "
        "{%0,%1,%2,%3}, {%4,%5,%6,%7}, {%8,%9}, {%0,%1,%2,%3};"
        : "+f"(c[0]), "+f"(c[1]), "+f"(c[2]), "+f"(c[3])
        : "r"(a[0]), "r"(a[1]), "r"(a[2]), "r"(a[3]), "r"(b[0]), "r"(b[1]));
}

#define ASZ  (128 * 36)
#define GEMM_SMEM (4 * ASZ * 4)
#define NIT  (D_ / 32)

// ---------------- shared GEMM core (tf32 mma.sync, 128x128x32, 8 warps) ----------------
struct GemmAcc { float a[2][8][4]; };

__device__ __forceinline__ void gemm_core(const float* __restrict__ Xa,
                                          const float* __restrict__ Wb,
                                          float* sm, int tid, GemmAcc& acc)
{
    const int wid = tid >> 5, lane = tid & 31;
    const int wm = wid >> 1, wn = wid & 1;
    const int g = lane >> 2, t4 = lane & 3;

    #pragma unroll
    for (int am = 0; am < 2; am++)
        #pragma unroll
        for (int na = 0; na < 8; na++)
            #pragma unroll
            for (int q = 0; q < 4; q++) acc.a[am][na][q] = 0.f;

    auto load_stage = [&](int ck, int s) {
        float* As = sm + s * ASZ;
        float* Bs = sm + 2 * ASZ + s * ASZ;
        #pragma unroll
        for (int i = 0; i < 4; i++) {
            int id = tid + i * 256;
            int r = id >> 3, u = id & 7;
            uint32_t da = s2u(As + r * 36 + u * 4);
            uint32_t db = s2u(Bs + r * 36 + u * 4);
            asm volatile("cp.async.cg.shared.global [%0], [%1], 16;"
                         :: "r"(da), "l"(Xa + (size_t)r * D_ + ck * 32 + u * 4));
            asm volatile("cp.async.cg.shared.global [%0], [%1], 16;"
                         :: "r"(db), "l"(Wb + (size_t)r * D_ + ck * 32 + u * 4));
        }
        asm volatile("cp.async.commit_group;");
    };

    load_stage(0, 0);

    for (int it = 0; it < NIT; it++) {
        if (it + 1 < NIT) {
            load_stage(it + 1, (it + 1) & 1);
            asm volatile("cp.async.wait_group 1;");
        } else {
            asm volatile("cp.async.wait_group 0;");
        }
        __syncthreads();

        const float* As = sm + (it & 1) * ASZ;
        const float* Bs = sm + 2 * ASZ + (it & 1) * ASZ;

        #pragma unroll
        for (int kk = 0; kk < 4; kk++) {
            const int c0 = kk * 8 + t4;
            uint32_t a[2][4];
            #pragma unroll
            for (int am = 0; am < 2; am++) {
                int r = wm * 32 + am * 16 + g;
                a[am][0] = f2tf32(As[r * 36 + c0]);
                a[am][1] = f2tf32(As[(r + 8) * 36 + c0]);
                a[am][2] = f2tf32(As[r * 36 + c0 + 4]);
                a[am][3] = f2tf32(As[(r + 8) * 36 + c0 + 4]);
            }
            uint32_t b[8][2];
            #pragma unroll
            for (int na = 0; na < 8; na++) {
                int n = wn * 64 + na * 8 + g;
                b[na][0] = f2tf32(Bs[n * 36 + c0]);
                b[na][1] = f2tf32(Bs[n * 36 + c0 + 4]);
            }
            #pragma unroll
            for (int am = 0; am < 2; am++)
                #pragma unroll
                for (int na = 0; na < 8; na++)
                    mma_tf32_16x8x8(acc.a[am][na], a[am], b[na]);
        }
        __syncthreads();
    }
}

// Merged Q/K/V projection: grid (8, 64, 3). Writes head layout [b,h,l,hd],
// tf32-rounded; Q additionally pre-scaled by 0.125 (exact).
__global__ void __launch_bounds__(256, 2)
gemm_proj3(const float* __restrict__ q, const float* __restrict__ k,
           const float* __restrict__ v, const float* __restrict__ Wq,
           const float* __restrict__ Wk, const float* __restrict__ Wv,
           float* __restrict__ qh, float* __restrict__ kh, float* __restrict__ vh)
{
    extern __shared__ float sm[];
    const int tid = threadIdx.x;
    const int z = blockIdx.z;
    const int m0 = blockIdx.y * 128, n0 = blockIdx.x * 128;

    const float* X = (z == 0) ? q : (z == 1) ? k : v;
    const float* W = (z == 0) ? Wq : (z == 1) ? Wk : Wv;
    float* Y       = (z == 0) ? qh : (z == 1) ? kh : vh;
    const float scale = (z == 0) ? 0.125f : 1.0f;

    GemmAcc acc;
    gemm_core(X + (size_t)m0 * D_, W + (size_t)n0 * D_, sm, tid, acc);

    const int wid = tid >> 5, lane = tid & 31;
    const int wm = wid >> 1, wn = wid & 1;
    const int g = lane >> 2, t4 = lane & 3;

    #pragma unroll
    for (int am = 0; am < 2; am++) {
        int r = m0 + wm * 32 + am * 16 + g;
        int b = r >> 11, l = r & 2047;
        #pragma unroll
        for (int na = 0; na < 8; na++) {
            int n = n0 + wn * 64 + na * 8 + 2 * t4;
            int h = n >> 6, hd = n & 63;
            float* p0 = Y + (((size_t)b * H_ + h) * L_ + l) * HD_ + hd;
            p0[0] = __uint_as_float(f2tf32(acc.a[am][na][0])) * scale;
            p0[1] = __uint_as_float(f2tf32(acc.a[am][na][1])) * scale;
            float* p1 = Y + (((size_t)b * H_ + h) * L_ + (l + 8)) * HD_ + hd;
            p1[0] = __uint_as_float(f2tf32(acc.a[am][na][2])) * scale;
            p1[1] = __uint_as_float(f2tf32(acc.a[am][na][3])) * scale;
        }
    }
}

// Output projection: Y[m,n] = sum_k X[m,k] * W[n,k], plain [m,n] output.
__global__ void __launch_bounds__(256, 2)
gemm_out(const float* __restrict__ X, const float* __restrict__ W,
         float* __restrict__ Y)
{
    extern __shared__ float sm[];
    const int tid = threadIdx.x;
    const int m0 = blockIdx.y * 128, n0 = blockIdx.x * 128;

    GemmAcc acc;
    gemm_core(X + (size_t)m0 * D_, W + (size_t)n0 * D_, sm, tid, acc);

    const int wid = tid >> 5, lane = tid & 31;
    const int wm = wid >> 1, wn = wid & 1;
    const int g = lane >> 2, t4 = lane & 3;

    #pragma unroll
    for (int am = 0; am < 2; am++) {
        int r = m0 + wm * 32 + am * 16 + g;
        #pragma unroll
        for (int na = 0; na < 8; na++) {
            int n = n0 + wn * 64 + na * 8 + 2 * t4;
            float* p0 = Y + (size_t)r * D_ + n;
            p0[0] = acc.a[am][na][0]; p0[1] = acc.a[am][na][1];
            float* p1 = Y + (size_t)(r + 8) * D_ + n;
            p1[0] = acc.a[am][na][2]; p1[1] = acc.a[am][na][3];
        }
    }
}

// ---------------- tf32 mma.sync flash attention (persistent, snake-balanced) ----------------
// 296 blocks x 128 threads. Tile rank -> (qtile, bh), heavy tiles (large qtile) first.
// Per tile: Q 128 rows (32/warp), KV tiles of 64, double-buffered cp.async.
#define QP 68
#define KVST (64 * QP)
#define ATTN_SMEM ((128 * QP + 4 * KVST) * 4)
#define NBLK 296

__global__ void __launch_bounds__(128, 2) attn_mma(
        const float* __restrict__ qh, const float* __restrict__ kh,
        const float* __restrict__ vh, float* __restrict__ ao)
{
    extern __shared__ float sm[];
    float* Qs = sm;
    float* KV = sm + 128 * QP;

    const int tid = threadIdx.x;
    const int wid = tid >> 5, lane = tid & 31;
    const int g = lane >> 2, t4 = lane & 3;
    const int p = blockIdx.x;

    const int srcA = (lane & ~3) | (t4 >> 1);
    const int srcB = srcA + 2;

    #pragma unroll 1
    for (int round = 0; round < 4; round++) {
        int rank = (round == 0) ? p
                 : (round == 1) ? (591 - p)
                 : (round == 2) ? (592 + p)
                 : (1183 - p);
        if (rank >= 1024) continue;
        const int qt = 15 - (rank >> 6);     // heavy first
        const int bh = rank & 63;
        const int q0 = qt * 128;

        const float* Qb = qh + ((size_t)bh * L_ + q0) * HD_;
        const float* Kb = kh + (size_t)bh * L_ * HD_;
        const float* Vb = vh + (size_t)bh * L_ * HD_;

        __syncthreads();   // smem free from previous tile

        // Q tile -> smem (values already tf32-rounded & scaled)
        #pragma unroll
        for (int i = 0; i < 16; i++) {
            int e = tid + i * 128;
            int r = e >> 4, c4 = (e & 15) * 4;
            *(float4*)(Qs + r * QP + c4) = *(const float4*)(Qb + (size_t)r * 64 + c4);
        }

        auto ldkv = [&](int kt, int st) {
            float* Ks = KV + st * 2 * KVST;
            float* Vs = Ks + KVST;
            const float* kg = Kb + (size_t)kt * 64 * 64;
            const float* vg = Vb + (size_t)kt * 64 * 64;
            #pragma unroll
            for (int i = 0; i < 8; i++) {
                int e = tid + i * 128;
                int r = e >> 4, c = (e & 15) * 4;
                asm volatile("cp.async.cg.shared.global [%0], [%1], 16;"
                             :: "r"(s2u(Ks + r * QP + c)), "l"(kg + (size_t)r * 64 + c));
                asm volatile("cp.async.cg.shared.global [%0], [%1], 16;"
                             :: "r"(s2u(Vs + r * QP + c)), "l"(vg + (size_t)r * 64 + c));
            }
            asm volatile("cp.async.commit_group;");
        };

        float mrun[4], lrun[4], O[2][8][4];
        #pragma unroll
        for (int i = 0; i < 4; i++) { mrun[i] = -1e30f; lrun[i] = 0.f; }
        #pragma unroll
        for (int mt = 0; mt < 2; mt++)
            #pragma unroll
            for (int nt = 0; nt < 8; nt++)
                #pragma unroll
                for (int e = 0; e < 4; e++) O[mt][nt][e] = 0.f;

        const int ntiles = 2 * qt + 2;
        ldkv(0, 0);

        for (int kt = 0; kt < ntiles; kt++) {
            asm volatile("cp.async.wait_group 0;");
            __syncthreads();
            if (kt + 1 < ntiles) ldkv(kt + 1, (kt + 1) & 1);
            const float* Ks = KV + (kt & 1) * 2 * KVST;
            const float* Vs = Ks + KVST;

            // ---- S = Q K^T (operands pre-rounded tf32) ----
            float S[2][8][4];
            #pragma unroll
            for (int mt = 0; mt < 2; mt++)
                #pragma unroll
                for (int nt = 0; nt < 8; nt++)
                    #pragma unroll
                    for (int e = 0; e < 4; e++) S[mt][nt][e] = 0.f;

            #pragma unroll
            for (int kc = 0; kc < 8; kc++) {
                uint32_t af[2][4];
                #pragma unroll
                for (int mt = 0; mt < 2; mt++) {
                    int r = wid * 32 + mt * 16 + g;
                    af[mt][0] = __float_as_uint(Qs[r * QP + kc * 8 + t4]);
                    af[mt][1] = __float_as_uint(Qs[(r + 8) * QP + kc * 8 + t4]);
                    af[mt][2] = __float_as_uint(Qs[r * QP + kc * 8 + t4 + 4]);
                    af[mt][3] = __float_as_uint(Qs[(r + 8) * QP + kc * 8 + t4 + 4]);
                }
                #pragma unroll
                for (int nt = 0; nt < 8; nt++) {
                    uint32_t bf[2];
                    bf[0] = __float_as_uint(Ks[(nt * 8 + g) * QP + kc * 8 + t4]);
                    bf[1] = __float_as_uint(Ks[(nt * 8 + g) * QP + kc * 8 + t4 + 4]);
                    mma_tf32_16x8x8(S[0][nt], af[0], bf);
                    mma_tf32_16x8x8(S[1][nt], af[1], bf);
                }
            }

            // ---- online softmax (Q pre-scaled; no per-element scaling) ----
            const bool maskt = (kt >= ntiles - 2);
            #pragma unroll
            for (int mt = 0; mt < 2; mt++)
                #pragma unroll
                for (int rr = 0; rr < 2; rr++) {
                    const int si = mt * 2 + rr;
                    const int rowg = q0 + wid * 32 + mt * 16 + rr * 8 + g;
                    float mloc = -1e30f;
                    #pragma unroll
                    for (int nt = 0; nt < 8; nt++)
                        #pragma unroll
                        for (int e = 0; e < 2; e++) {
                            float vv = S[mt][nt][rr * 2 + e];
                            if (maskt && (kt * 64 + nt * 8 + 2 * t4 + e) > rowg) vv = -1e30f;
                            S[mt][nt][rr * 2 + e] = vv;
                            mloc = fmaxf(mloc, vv);
                        }
                    mloc = fmaxf(mloc, __shfl_xor_sync(0xffffffffu, mloc, 1));
                    mloc = fmaxf(mloc, __shfl_xor_sync(0xffffffffu, mloc, 2));
                    float mnew = fmaxf(mrun[si], mloc);
                    float corr = __expf(mrun[si] - mnew);
                    float sum = 0.f;
                    #pragma unroll
                    for (int nt = 0; nt < 8; nt++)
                        #pragma unroll
                        for (int e = 0; e < 2; e++) {
                            float pe = __expf(S[mt][nt][rr * 2 + e] - mnew);
                            S[mt][nt][rr * 2 + e] = pe;
                            sum += pe;
                        }
                    sum += __shfl_xor_sync(0xffffffffu, sum, 1);
                    sum += __shfl_xor_sync(0xffffffffu, sum, 2);
                    lrun[si] = lrun[si] * corr + sum;
                    mrun[si] = mnew;
                    #pragma unroll
                    for (int nt = 0; nt < 8; nt++)
                        #pragma unroll
                        for (int e = 0; e < 2; e++)
                            O[mt][nt][rr * 2 + e] *= corr;
                }

            // ---- P -> tf32 in place ----
            #pragma unroll
            for (int mt = 0; mt < 2; mt++)
                #pragma unroll
                for (int nt = 0; nt < 8; nt++)
                    #pragma unroll
                    for (int e = 0; e < 4; e++)
                        S[mt][nt][e] = __uint_as_float(f2tf32(S[mt][nt][e]));

            // ---- O += P V  (C-frag -> A-frag via quad shuffles) ----
            #pragma unroll
            for (int kc = 0; kc < 8; kc++) {
                uint32_t a[2][4];
                #pragma unroll
                for (int mt = 0; mt < 2; mt++) {
                    float v0 = __shfl_sync(0xffffffffu, S[mt][kc][0], srcA);
                    float v1 = __shfl_sync(0xffffffffu, S[mt][kc][1], srcA);
                    float v2 = __shfl_sync(0xffffffffu, S[mt][kc][2], srcA);
                    float v3 = __shfl_sync(0xffffffffu, S[mt][kc][3], srcA);
                    float w0 = __shfl_sync(0xffffffffu, S[mt][kc][0], srcB);
                    float w1 = __shfl_sync(0xffffffffu, S[mt][kc][1], srcB);
                    float w2 = __shfl_sync(0xffffffffu, S[mt][kc][2], srcB);
                    float w3 = __shfl_sync(0xffffffffu, S[mt][kc][3], srcB);
                    a[mt][0] = __float_as_uint((t4 & 1) ? v1 : v0);
                    a[mt][1] = __float_as_uint((t4 & 1) ? v3 : v2);
                    a[mt][2] = __float_as_uint((t4 & 1) ? w1 : w0);
                    a[mt][3] = __float_as_uint((t4 & 1) ? w3 : w2);
                }
                #pragma unroll
                for (int nt = 0; nt < 8; nt++) {
                    uint32_t bf[2];
                    bf[0] = __float_as_uint(Vs[(kc * 8 + t4) * QP + nt * 8 + g]);
                    bf[1] = __float_as_uint(Vs[(kc * 8 + t4 + 4) * QP + nt * 8 + g]);
                    mma_tf32_16x8x8(O[0][nt], a[0], bf);
                    mma_tf32_16x8x8(O[1][nt], a[1], bf);
                }
            }
        }

        // ---- epilogue: normalize + write [b, l, d] ----
        const int b = bh >> 4, h = bh & 15;
        #pragma unroll
        for (int mt = 0; mt < 2; mt++)
            #pragma unroll
            for (int rr = 0; rr < 2; rr++) {
                const int si = mt * 2 + rr;
                float inv = 1.f / lrun[si];
                int row = q0 + wid * 32 + mt * 16 + rr * 8 + g;
                float* op = ao + ((size_t)b * L_ + row) * D_ + h * 64 + 2 * t4;
                #pragma unroll
                for (int nt = 0; nt < 8; nt++) {
                    float2 w = make_float2(O[mt][nt][rr * 2] * inv, O[mt][nt][rr * 2 + 1] * inv);
                    *(float2*)(op + nt * 8) = w;
                }
            }
    }
}

// ---------------- launch ----------------
extern "C" void kernel_launch(void* const* d_in, const int* in_sizes, int n_in,
                              void* d_out, int out_size)
{
    const float* q  = (const float*)d_in[0];
    const float* k  = (const float*)d_in[1];
    const float* v  = (const float*)d_in[2];
    // d_in[3] = mask (causal tril) — applied analytically
    const float* Wq = (const float*)d_in[4];
    const float* Wk = (const float*)d_in[5];
    const float* Wv = (const float*)d_in[6];
    const float* Wo = (const float*)d_in[7];
    float* out = (float*)d_out;

    float *qh, *kh, *vh, *ao;
    cudaGetSymbolAddress((void**)&qh, g_qh);
    cudaGetSymbolAddress((void**)&kh, g_kh);
    cudaGetSymbolAddress((void**)&vh, g_vh);
    cudaGetSymbolAddress((void**)&ao, g_ao);

    cudaFuncSetAttribute(gemm_proj3, cudaFuncAttributeMaxDynamicSharedMemorySize, GEMM_SMEM);
    cudaFuncSetAttribute(gemm_out, cudaFuncAttributeMaxDynamicSharedMemorySize, GEMM_SMEM);
    cudaFuncSetAttribute(attn_mma, cudaFuncAttributeMaxDynamicSharedMemorySize, ATTN_SMEM);

    gemm_proj3<<<dim3(D_ / 128, (B_ * L_) / 128, 3), 256, GEMM_SMEM>>>(
        q, k, v, Wq, Wk, Wv, qh, kh, vh);
    attn_mma<<<NBLK, 128, ATTN_SMEM>>>(qh, kh, vh, ao);
    gemm_out<<<dim3(D_ / 128, (B_ * L_) / 128), 256, GEMM_SMEM>>>(ao, Wo, out);
}